// round 4
// baseline (speedup 1.0000x reference)
#include <cuda_runtime.h>

#define N_NODES 100000
#define F_DIM   64
#define N_EDGES 1000000
#define ALPHA   0.1f
#define BETA    0.5f
#define CAP     64       // max in-degree; Poisson(10), max over 100k ~30

#define TILE_N   128     // nodes per fused block
#define S_STRIDE 66      // even (float2-aligned), conflict-free

// Scratch (__device__ globals; cudaMalloc forbidden)
__device__ float               g_Wp[F_DIM * F_DIM];              // W' = 0.5W + 0.5I
__device__ int                 g_cnt[N_NODES];
__device__ unsigned long long  g_bucket[(size_t)N_NODES * CAP];  // (val<<32)|src

// ---------------------------------------------------------------------------
// K0: zero counters + W' = BETA*W + (1-BETA)*I
// ---------------------------------------------------------------------------
__global__ void prep_kernel(const float* __restrict__ W) {
    int i = blockIdx.x * blockDim.x + threadIdx.x;
    if (i < N_NODES) g_cnt[i] = 0;
    if (i < F_DIM * F_DIM) {
        int r = i >> 6, c = i & 63;
        float v = BETA * W[i];
        if (r == c) v += (1.0f - BETA);
        g_Wp[i] = v;
    }
}

// ---------------------------------------------------------------------------
// K1: bucket fill — int atomics only
// ---------------------------------------------------------------------------
__global__ void fill_kernel(const int*   __restrict__ src,
                            const int*   __restrict__ dst,
                            const float* __restrict__ val) {
    int e = blockIdx.x * blockDim.x + threadIdx.x;
    if (e >= N_EDGES) return;
    int d = dst[e];
    int pos = atomicAdd(&g_cnt[d], 1);
    if (pos < CAP) {
        unsigned long long p =
            ((unsigned long long)__float_as_uint((1.0f - ALPHA) * val[e]) << 32)
            | (unsigned int)src[e];
        g_bucket[(size_t)d * CAP + pos] = p;
    }
}

// ---------------------------------------------------------------------------
// K2: FUSED gather + GEMM + ReLU.
// Phase A: 8 warps x 16 nodes each gather support rows into smem
//          (float2 loads, bucket prefetched 2 ahead, feature row 1 ahead).
// Phase B: register-tiled GEMM: thread = 4 nodes x 8 cols, f32x2 FMA.
// ---------------------------------------------------------------------------
__global__ void __launch_bounds__(256, 3)
fused_kernel(const float* __restrict__ feat,
             const float* __restrict__ f0,
             float*       __restrict__ out) {
    extern __shared__ float smem[];
    float* Wsh = smem;                    // 64*64 = 16 KB
    float* Ssh = smem + F_DIM * F_DIM;    // TILE_N * S_STRIDE = 33.8 KB

    int tid  = threadIdx.x;
    int base = blockIdx.x * TILE_N;
    int warp = tid >> 5, lane = tid & 31;

    // W' -> smem (float4 x 4 per thread)
    {
        const float4* w4 = reinterpret_cast<const float4*>(g_Wp);
        float4* d4 = reinterpret_cast<float4*>(Wsh);
        #pragma unroll
        for (int j = 0; j < 4; j++) d4[tid + j * 256] = w4[tid + j * 256];
    }

    // ---- Phase A: gather 16 nodes per warp ----
    const float2* feat2 = reinterpret_cast<const float2*>(feat);
    const float2* f02   = reinterpret_cast<const float2*>(f0);

    for (int i = 0; i < 16; i++) {
        int nl   = warp * 16 + i;
        int node = base + nl;
        if (node >= N_NODES) break;

        float2 fv = __ldg(&f02[(size_t)node * 32 + lane]);
        float ax = ALPHA * fv.x;
        float ay = ALPHA * fv.y;

        int cnt = min(g_cnt[node], CAP);
        const unsigned long long* bk = &g_bucket[(size_t)node * CAP];

        if (cnt > 0) {
            unsigned long long p  = bk[0];
            unsigned long long pn = (cnt > 1) ? bk[1] : 0ull;
            float2 f = feat2[(size_t)(unsigned)(p & 0xffffffffu) * 32 + lane];
            for (int e = 0; e < cnt; e++) {
                unsigned long long p2 = (e + 2 < cnt) ? bk[e + 2] : 0ull;
                // next feature row (address ready: pn prefetched last iter)
                float2 fn = feat2[(size_t)(unsigned)(pn & 0xffffffffu) * 32 + lane];
                float w = __uint_as_float((unsigned)(p >> 32));
                ax = fmaf(w, f.x, ax);
                ay = fmaf(w, f.y, ay);
                p = pn; pn = p2; f = fn;
            }
        }
        // float2 store, stride-66 rows -> conflict-free
        *reinterpret_cast<float2*>(&Ssh[nl * S_STRIDE + 2 * lane]) =
            make_float2(ax, ay);
    }
    __syncthreads();

    // ---- Phase B: GEMM + ReLU ----
    int ng4 = (tid >> 3) * 4;   // 4 nodes per thread (0..124)
    int cg8 = (tid & 7) * 8;    // 8 cols per thread  (0..56)

    unsigned long long acc[16];
    #pragma unroll
    for (int i = 0; i < 16; i++) acc[i] = 0ull;

    #pragma unroll 8
    for (int k = 0; k < F_DIM; k++) {
        const unsigned long long* wp =
            reinterpret_cast<const unsigned long long*>(&Wsh[k * F_DIM + cg8]);
        unsigned long long w0 = wp[0], w1 = wp[1], w2 = wp[2], w3 = wp[3];
        #pragma unroll
        for (int n = 0; n < 4; n++) {
            float s = Ssh[(ng4 + n) * S_STRIDE + k];
            unsigned long long s2;
            asm("mov.b64 %0, {%1, %1};" : "=l"(s2) : "f"(s));
            asm("fma.rn.f32x2 %0, %1, %2, %0;" : "+l"(acc[n*4+0]) : "l"(s2), "l"(w0));
            asm("fma.rn.f32x2 %0, %1, %2, %0;" : "+l"(acc[n*4+1]) : "l"(s2), "l"(w1));
            asm("fma.rn.f32x2 %0, %1, %2, %0;" : "+l"(acc[n*4+2]) : "l"(s2), "l"(w2));
            asm("fma.rn.f32x2 %0, %1, %2, %0;" : "+l"(acc[n*4+3]) : "l"(s2), "l"(w3));
        }
    }

    #pragma unroll
    for (int n = 0; n < 4; n++) {
        int node = base + ng4 + n;
        if (node >= N_NODES) break;
        float r[8];
        #pragma unroll
        for (int p = 0; p < 4; p++) {
            float lo, hi;
            asm("mov.b64 {%0, %1}, %2;" : "=f"(lo), "=f"(hi) : "l"(acc[n*4+p]));
            r[2*p]   = fmaxf(lo, 0.0f);
            r[2*p+1] = fmaxf(hi, 0.0f);
        }
        float4* o4 = reinterpret_cast<float4*>(&out[(size_t)node * F_DIM + cg8]);
        o4[0] = make_float4(r[0], r[1], r[2], r[3]);
        o4[1] = make_float4(r[4], r[5], r[6], r[7]);
    }
}

// ---------------------------------------------------------------------------
// inputs: 0=features, 1=features0, 2=edge_src, 3=edge_dst, 4=edge_vals, 5=W
// ---------------------------------------------------------------------------
extern "C" void kernel_launch(void* const* d_in, const int* in_sizes, int n_in,
                              void* d_out, int out_size) {
    const float* features  = (const float*)d_in[0];
    const float* features0 = (const float*)d_in[1];
    const int*   edge_src  = (const int*)d_in[2];
    const int*   edge_dst  = (const int*)d_in[3];
    const float* edge_vals = (const float*)d_in[4];
    const float* W         = (const float*)d_in[5];
    float* out = (float*)d_out;

    prep_kernel<<<(N_NODES + 255) / 256, 256>>>(W);
    fill_kernel<<<(N_EDGES + 255) / 256, 256>>>(edge_src, edge_dst, edge_vals);

    int smem_bytes = (F_DIM * F_DIM + TILE_N * S_STRIDE) * sizeof(float); // 50.2 KB
    cudaFuncSetAttribute(fused_kernel,
                         cudaFuncAttributeMaxDynamicSharedMemorySize, smem_bytes);
    fused_kernel<<<(N_NODES + TILE_N - 1) / TILE_N, 256, smem_bytes>>>(
        features, features0, out);
}

// round 5
// speedup vs baseline: 1.1519x; 1.1519x over previous
#include <cuda_runtime.h>

#define N_NODES 100000
#define F_DIM   64
#define N_EDGES 1000000
#define ALPHA   0.1f
#define BETA    0.5f
#define CAP     64       // max in-degree; Poisson(10), max over 100k ~30

#define TILE_N   128     // nodes per GEMM block
#define S_STRIDE 66      // float2-aligned padded stride, conflict-free

// Scratch (__device__ globals; cudaMalloc forbidden)
__device__ float               g_support[N_NODES * F_DIM];       // 25.6 MB
__device__ float               g_Wp[F_DIM * F_DIM];
__device__ int                 g_cnt[N_NODES];
__device__ unsigned long long  g_bucket[(size_t)N_NODES * CAP];  // (val<<32)|src

// ---------------------------------------------------------------------------
// K0: zero counters + W' = BETA*W + (1-BETA)*I
// ---------------------------------------------------------------------------
__global__ void prep_kernel(const float* __restrict__ W) {
    int i = blockIdx.x * blockDim.x + threadIdx.x;
    // zero counters, int4-wide (N_NODES = 100000 = 25000 * 4)
    if (i < N_NODES / 4)
        reinterpret_cast<int4*>(g_cnt)[i] = make_int4(0, 0, 0, 0);
    if (i < F_DIM * F_DIM) {
        int r = i >> 6, c = i & 63;
        float v = BETA * W[i];
        if (r == c) v += (1.0f - BETA);
        g_Wp[i] = v;
    }
}

// ---------------------------------------------------------------------------
// K1: bucket fill — 4 edges per thread, vectorized edge loads, int atomics.
// ---------------------------------------------------------------------------
__global__ void fill_kernel(const int4*   __restrict__ src4,
                            const int4*   __restrict__ dst4,
                            const float4* __restrict__ val4) {
    int t = blockIdx.x * blockDim.x + threadIdx.x;
    if (t >= N_EDGES / 4) return;   // N_EDGES divisible by 4
    int4   s = src4[t];
    int4   d = dst4[t];
    float4 v = val4[t];

    #pragma unroll
    for (int j = 0; j < 4; j++) {
        int   dd = (j == 0) ? d.x : (j == 1) ? d.y : (j == 2) ? d.z : d.w;
        int   ss = (j == 0) ? s.x : (j == 1) ? s.y : (j == 2) ? s.z : s.w;
        float vv = (j == 0) ? v.x : (j == 1) ? v.y : (j == 2) ? v.z : v.w;
        int pos = atomicAdd(&g_cnt[dd], 1);
        if (pos < CAP) {
            unsigned long long p =
                ((unsigned long long)__float_as_uint((1.0f - ALPHA) * vv) << 32)
                | (unsigned int)ss;
            g_bucket[(size_t)dd * CAP + pos] = p;
        }
    }
}

// ---------------------------------------------------------------------------
// K2: gather — one warp per node, float2 row loads, 2-edge software pipeline.
//     acc starts at ALPHA*features0. Lane owns cols {2*lane, 2*lane+1}.
// ---------------------------------------------------------------------------
__global__ void __launch_bounds__(256) gather_kernel(const float2* __restrict__ feat2,
                                                     const float2* __restrict__ f02) {
    int node = (blockIdx.x * blockDim.x + threadIdx.x) >> 5;
    int lane = threadIdx.x & 31;
    if (node >= N_NODES) return;

    float2 fv = __ldg(&f02[(size_t)node * 32 + lane]);
    float ax = ALPHA * fv.x;
    float ay = ALPHA * fv.y;

    int cnt = min(g_cnt[node], CAP);
    const unsigned long long* bk = &g_bucket[(size_t)node * CAP];

    if (cnt > 0) {
        unsigned long long p0 = bk[0];
        unsigned long long p1 = (cnt > 1) ? bk[1] : p0;
        float2 r0 = feat2[(size_t)(unsigned)(p0 & 0xffffffffu) * 32 + lane];
        float2 r1 = feat2[(size_t)(unsigned)(p1 & 0xffffffffu) * 32 + lane];

        int e = 0;
        for (; e + 2 < cnt; e += 2) {
            unsigned long long p2 = bk[e + 2];
            unsigned long long p3 = (e + 3 < cnt) ? bk[e + 3] : p2;
            float2 r2 = feat2[(size_t)(unsigned)(p2 & 0xffffffffu) * 32 + lane];
            float2 r3 = feat2[(size_t)(unsigned)(p3 & 0xffffffffu) * 32 + lane];
            float w0 = __uint_as_float((unsigned)(p0 >> 32));
            float w1 = __uint_as_float((unsigned)(p1 >> 32));
            ax = fmaf(w0, r0.x, ax);  ay = fmaf(w0, r0.y, ay);
            ax = fmaf(w1, r1.x, ax);  ay = fmaf(w1, r1.y, ay);
            p0 = p2; p1 = p3; r0 = r2; r1 = r3;
        }
        // drain (1 or 2 remaining)
        float w0 = __uint_as_float((unsigned)(p0 >> 32));
        ax = fmaf(w0, r0.x, ax);  ay = fmaf(w0, r0.y, ay);
        if (e + 1 < cnt) {
            float w1 = __uint_as_float((unsigned)(p1 >> 32));
            ax = fmaf(w1, r1.x, ax);  ay = fmaf(w1, r1.y, ay);
        }
    }
    reinterpret_cast<float2*>(g_support)[(size_t)node * 32 + lane] =
        make_float2(ax, ay);
}

// ---------------------------------------------------------------------------
// K3: out = relu(support @ W')
// 256 threads, 128-node tile, thread = 4 nodes x 8 cols, f32x2 FMA.
// smem 50.2 KB -> 3 blocks/SM.
// ---------------------------------------------------------------------------
__global__ void __launch_bounds__(256, 3) gemm_relu_kernel(float* __restrict__ out) {
    extern __shared__ float smem[];
    float* Wsh = smem;                    // 16 KB
    float* Ssh = smem + F_DIM * F_DIM;    // 128*66*4 = 33.8 KB

    int tid  = threadIdx.x;
    int base = blockIdx.x * TILE_N;

    // W' -> smem
    {
        const float4* w4 = reinterpret_cast<const float4*>(g_Wp);
        float4* d4 = reinterpret_cast<float4*>(Wsh);
        #pragma unroll
        for (int j = 0; j < 4; j++) d4[tid + j * 256] = w4[tid + j * 256];
    }
    // Stage 128 support rows: float2 coalesced LDG -> padded STS
    // i in [0, 128*32): node-local nl = i>>5, float2-col = i&31
    #pragma unroll 4
    for (int i = tid; i < TILE_N * 32; i += 256) {
        int nl = i >> 5, c2 = i & 31;
        int node = base + nl;
        float2 v = (node < N_NODES)
            ? __ldg(&reinterpret_cast<const float2*>(g_support)[(size_t)node * 32 + c2])
            : make_float2(0.0f, 0.0f);
        *reinterpret_cast<float2*>(&Ssh[nl * S_STRIDE + 2 * c2]) = v;
    }
    __syncthreads();

    int ng4 = (tid >> 3) * 4;   // 4 nodes (0..124)
    int cg8 = (tid & 7) * 8;    // 8 cols  (0..56)

    unsigned long long acc[16];
    #pragma unroll
    for (int i = 0; i < 16; i++) acc[i] = 0ull;

    #pragma unroll 8
    for (int k = 0; k < F_DIM; k++) {
        const unsigned long long* wp =
            reinterpret_cast<const unsigned long long*>(&Wsh[k * F_DIM + cg8]);
        unsigned long long w0 = wp[0], w1 = wp[1], w2 = wp[2], w3 = wp[3];
        #pragma unroll
        for (int n = 0; n < 4; n++) {
            float s = Ssh[(ng4 + n) * S_STRIDE + k];
            unsigned long long s2;
            asm("mov.b64 %0, {%1, %1};" : "=l"(s2) : "f"(s));
            asm("fma.rn.f32x2 %0, %1, %2, %0;" : "+l"(acc[n*4+0]) : "l"(s2), "l"(w0));
            asm("fma.rn.f32x2 %0, %1, %2, %0;" : "+l"(acc[n*4+1]) : "l"(s2), "l"(w1));
            asm("fma.rn.f32x2 %0, %1, %2, %0;" : "+l"(acc[n*4+2]) : "l"(s2), "l"(w2));
            asm("fma.rn.f32x2 %0, %1, %2, %0;" : "+l"(acc[n*4+3]) : "l"(s2), "l"(w3));
        }
    }

    #pragma unroll
    for (int n = 0; n < 4; n++) {
        int node = base + ng4 + n;
        if (node >= N_NODES) break;
        float r[8];
        #pragma unroll
        for (int p = 0; p < 4; p++) {
            float lo, hi;
            asm("mov.b64 {%0, %1}, %2;" : "=f"(lo), "=f"(hi) : "l"(acc[n*4+p]));
            r[2*p]   = fmaxf(lo, 0.0f);
            r[2*p+1] = fmaxf(hi, 0.0f);
        }
        float4* o4 = reinterpret_cast<float4*>(&out[(size_t)node * F_DIM + cg8]);
        o4[0] = make_float4(r[0], r[1], r[2], r[3]);
        o4[1] = make_float4(r[4], r[5], r[6], r[7]);
    }
}

// ---------------------------------------------------------------------------
// inputs: 0=features, 1=features0, 2=edge_src, 3=edge_dst, 4=edge_vals, 5=W
// ---------------------------------------------------------------------------
extern "C" void kernel_launch(void* const* d_in, const int* in_sizes, int n_in,
                              void* d_out, int out_size) {
    const float* features  = (const float*)d_in[0];
    const float* features0 = (const float*)d_in[1];
    const int*   edge_src  = (const int*)d_in[2];
    const int*   edge_dst  = (const int*)d_in[3];
    const float* edge_vals = (const float*)d_in[4];
    const float* W         = (const float*)d_in[5];
    float* out = (float*)d_out;

    prep_kernel<<<(N_NODES / 4 + 255) / 256, 256>>>(W);

    fill_kernel<<<(N_EDGES / 4 + 255) / 256, 256>>>(
        reinterpret_cast<const int4*>(edge_src),
        reinterpret_cast<const int4*>(edge_dst),
        reinterpret_cast<const float4*>(edge_vals));

    long long gthreads = (long long)N_NODES * 32;
    gather_kernel<<<(int)((gthreads + 255) / 256), 256>>>(
        reinterpret_cast<const float2*>(features),
        reinterpret_cast<const float2*>(features0));

    int smem_bytes = (F_DIM * F_DIM + TILE_N * S_STRIDE) * sizeof(float); // 50.2 KB
    cudaFuncSetAttribute(gemm_relu_kernel,
                         cudaFuncAttributeMaxDynamicSharedMemorySize, smem_bytes);
    gemm_relu_kernel<<<(N_NODES + TILE_N - 1) / TILE_N, 256, smem_bytes>>>(out);
}

// round 8
// speedup vs baseline: 1.3036x; 1.1317x over previous
#include <cuda_runtime.h>
#include <cuda_bf16.h>
#include <cstdint>

#define N_NODES 100000
#define F_DIM   64
#define N_EDGES 1000000
#define ALPHA   0.1f
#define BETA    0.5f
#define CAP     64
#define N_GROUPS (N_NODES / 16)          // 6250, exact

// Scratch (__device__ globals; cudaMalloc forbidden)
__device__ int                 g_cnt[N_NODES];
__device__ unsigned long long  g_bucket[(size_t)N_NODES * CAP];   // (val<<32)|src
// A fragments: [group][kchunk(4)][hl(2)] -> 512B chunk = 32 lanes x {a0,a1,a2,a3}
__device__ uint32_t            g_Af[(size_t)N_GROUPS * 1024];     // 25.6 MB
// B fragments: [(kchunk*8+nb)*2+hl] -> 32 lanes x {b0,b1} (uint2)
__device__ uint2               g_Bf[64 * 32];                     // 16 KB

// ---------------------------------------------------------------------------
// K0: zero counters + build W' B-fragments (bf16 hi/lo, pre-packed)
//     B[k][n] = BETA*W[k][n] + (1-BETA)*(k==n)
//     b0 = (B[k0][n], B[k0+1][n]),  b1 = (B[k0+8][n], B[k0+9][n])
//     k0 = c*16 + (lane%4)*2,  n = nb*8 + lane/4
// ---------------------------------------------------------------------------
__device__ __forceinline__ float wprime(const float* W, int k, int n) {
    return BETA * W[k * 64 + n] + ((k == n) ? (1.0f - BETA) : 0.0f);
}
__global__ void prep_kernel(const float* __restrict__ W) {
    int i = blockIdx.x * blockDim.x + threadIdx.x;
    if (i < N_NODES / 4)
        reinterpret_cast<int4*>(g_cnt)[i] = make_int4(0, 0, 0, 0);
    if (i < 1024) {                       // (c, nb, lane)
        int c    = i >> 8;
        int nb   = (i >> 5) & 7;
        int lane = i & 31;
        int n  = nb * 8 + (lane >> 2);
        int k0 = c * 16 + (lane & 3) * 2;

        float v[4] = { wprime(W, k0, n),     wprime(W, k0 + 1, n),
                       wprime(W, k0 + 8, n), wprime(W, k0 + 9, n) };
        uint32_t hp[2], lp[2];
        #pragma unroll
        for (int r = 0; r < 2; r++) {
            __nv_bfloat16 h0 = __float2bfloat16(v[r*2+0]);
            __nv_bfloat16 h1 = __float2bfloat16(v[r*2+1]);
            __nv_bfloat16 l0 = __float2bfloat16(v[r*2+0] - __bfloat162float(h0));
            __nv_bfloat16 l1 = __float2bfloat16(v[r*2+1] - __bfloat162float(h1));
            hp[r] = ((uint32_t)__bfloat16_as_ushort(h1) << 16) | __bfloat16_as_ushort(h0);
            lp[r] = ((uint32_t)__bfloat16_as_ushort(l1) << 16) | __bfloat16_as_ushort(l0);
        }
        int base = (c * 8 + nb) * 2;
        g_Bf[(base + 0) * 32 + lane] = make_uint2(hp[0], hp[1]);
        g_Bf[(base + 1) * 32 + lane] = make_uint2(lp[0], lp[1]);
    }
}

// ---------------------------------------------------------------------------
// K1: bucket fill — scalar, int atomics
// ---------------------------------------------------------------------------
__global__ void fill_kernel(const int*   __restrict__ src,
                            const int*   __restrict__ dst,
                            const float* __restrict__ val) {
    int e = blockIdx.x * blockDim.x + threadIdx.x;
    if (e >= N_EDGES) return;
    int d = dst[e];
    int pos = atomicAdd(&g_cnt[d], 1);
    if (pos < CAP) {
        unsigned long long p =
            ((unsigned long long)__float_as_uint((1.0f - ALPHA) * val[e]) << 32)
            | (unsigned int)src[e];
        g_bucket[(size_t)d * CAP + pos] = p;
    }
}

// ---------------------------------------------------------------------------
// K2: gather — one warp per node; acc = ALPHA*f0 + sum w*feat[src].
//     Lane owns col-pair (2*lane, 2*lane+1); result written hi/lo bf16
//     directly into A-fragment cells.
//     kchunk c = lane/8, pair-in-chunk p = lane%8
//     target mma-lane m = (r%8)*4 + (p%4);  reg q = (r>=8) + 2*(p>=4)
// ---------------------------------------------------------------------------
__global__ void __launch_bounds__(256) gather_kernel(const float2* __restrict__ feat2,
                                                     const float2* __restrict__ f02) {
    int node = (blockIdx.x * blockDim.x + threadIdx.x) >> 5;
    int lane = threadIdx.x & 31;
    if (node >= N_NODES) return;

    float2 fv = __ldg(&f02[(size_t)node * 32 + lane]);
    float ax = ALPHA * fv.x;
    float ay = ALPHA * fv.y;

    int cnt = min(g_cnt[node], CAP);
    const unsigned long long* bk = &g_bucket[(size_t)node * CAP];

    if (cnt > 0) {
        unsigned long long p  = bk[0];
        unsigned long long pn = (cnt > 1) ? bk[1] : 0ull;
        float2 f = feat2[(size_t)(unsigned)(p & 0xffffffffu) * 32 + lane];
        for (int e = 0; e < cnt; e++) {
            unsigned long long p2 = (e + 2 < cnt) ? bk[e + 2] : 0ull;
            float2 fn = feat2[(size_t)(unsigned)(pn & 0xffffffffu) * 32 + lane];
            float w = __uint_as_float((unsigned)(p >> 32));
            ax = fmaf(w, f.x, ax);
            ay = fmaf(w, f.y, ay);
            p = pn; pn = p2; f = fn;
        }
    }

    // hi/lo split + pack (even column in low 16 bits)
    __nv_bfloat16 hx = __float2bfloat16(ax);
    __nv_bfloat16 hy = __float2bfloat16(ay);
    __nv_bfloat16 lx = __float2bfloat16(ax - __bfloat162float(hx));
    __nv_bfloat16 ly = __float2bfloat16(ay - __bfloat162float(hy));
    uint32_t hp = ((uint32_t)__bfloat16_as_ushort(hy) << 16) | __bfloat16_as_ushort(hx);
    uint32_t lp = ((uint32_t)__bfloat16_as_ushort(ly) << 16) | __bfloat16_as_ushort(lx);

    int g = node >> 4, r = node & 15;
    int c = lane >> 3, pp = lane & 7;
    int m = (r & 7) * 4 + (pp & 3);
    int q = ((r >> 3) & 1) + ((pp >> 2) << 1);
    uint32_t idx = (uint32_t)g * 1024 + (uint32_t)(c * 2) * 128 + m * 4 + q;
    g_Af[idx]       = hp;   // hl = 0
    g_Af[idx + 128] = lp;   // hl = 1
}

// ---------------------------------------------------------------------------
// K3: GEMM via mma.sync m16n8k16 bf16, 3-term split, + ReLU.
// One warp = 16 nodes. No smem, no syncs. A: 8x LDG.128; B: L1-hot LDG.64.
// ---------------------------------------------------------------------------
__device__ __forceinline__ void mma16816(float& d0, float& d1, float& d2, float& d3,
                                         uint4 a, uint2 b) {
    asm volatile(
        "mma.sync.aligned.m16n8k16.row.col.f32.bf16.bf16.f32 "
        "{%0,%1,%2,%3}, {%4,%5,%6,%7}, {%8,%9}, {%0,%1,%2,%3};"
        : "+f"(d0), "+f"(d1), "+f"(d2), "+f"(d3)
        : "r"(a.x), "r"(a.y), "r"(a.z), "r"(a.w), "r"(b.x), "r"(b.y));
}

__global__ void __launch_bounds__(256) mma_kernel(float* __restrict__ out) {
    int wg   = (blockIdx.x * 256 + threadIdx.x) >> 5;   // warp group id = 16 nodes
    int lane = threadIdx.x & 31;
    if (wg >= N_GROUPS) return;

    // FIX (round 7 bug): group stride is 1024 uint32 = 256 uint4, not 64.
    const uint4* A = reinterpret_cast<const uint4*>(g_Af) + (size_t)wg * 256;
    uint4 ah[4], al[4];
    #pragma unroll
    for (int c = 0; c < 4; c++) {
        ah[c] = __ldg(&A[(c * 2 + 0) * 32 + lane]);
        al[c] = __ldg(&A[(c * 2 + 1) * 32 + lane]);
    }

    int grp = lane >> 2, qp = lane & 3;
    int row0 = wg * 16 + grp;            // rows row0 and row0+8

    #pragma unroll
    for (int nb = 0; nb < 8; nb++) {
        float d0 = 0.f, d1 = 0.f, d2 = 0.f, d3 = 0.f;
        #pragma unroll
        for (int c = 0; c < 4; c++) {
            int base = (c * 8 + nb) * 2;
            uint2 bh = __ldg(&g_Bf[(base + 0) * 32 + lane]);
            uint2 bl = __ldg(&g_Bf[(base + 1) * 32 + lane]);
            mma16816(d0, d1, d2, d3, ah[c], bh);
            mma16816(d0, d1, d2, d3, ah[c], bl);
            mma16816(d0, d1, d2, d3, al[c], bh);
        }
        int col = nb * 8 + qp * 2;
        float2 v0 = make_float2(fmaxf(d0, 0.f), fmaxf(d1, 0.f));
        float2 v1 = make_float2(fmaxf(d2, 0.f), fmaxf(d3, 0.f));
        *reinterpret_cast<float2*>(&out[(size_t)row0 * F_DIM + col])       = v0;
        *reinterpret_cast<float2*>(&out[(size_t)(row0 + 8) * F_DIM + col]) = v1;
    }
}

// ---------------------------------------------------------------------------
// inputs: 0=features, 1=features0, 2=edge_src, 3=edge_dst, 4=edge_vals, 5=W
// ---------------------------------------------------------------------------
extern "C" void kernel_launch(void* const* d_in, const int* in_sizes, int n_in,
                              void* d_out, int out_size) {
    const float* features  = (const float*)d_in[0];
    const float* features0 = (const float*)d_in[1];
    const int*   edge_src  = (const int*)d_in[2];
    const int*   edge_dst  = (const int*)d_in[3];
    const float* edge_vals = (const float*)d_in[4];
    const float* W         = (const float*)d_in[5];
    float* out = (float*)d_out;

    prep_kernel<<<(N_NODES / 4 + 255) / 256, 256>>>(W);
    fill_kernel<<<(N_EDGES + 255) / 256, 256>>>(edge_src, edge_dst, edge_vals);

    long long gthreads = (long long)N_NODES * 32;
    gather_kernel<<<(int)((gthreads + 255) / 256), 256>>>(
        reinterpret_cast<const float2*>(features),
        reinterpret_cast<const float2*>(features0));

    int gwarps  = N_GROUPS;                       // 6250
    int gblocks = (gwarps * 32 + 255) / 256;      // 782
    mma_kernel<<<gblocks, 256>>>(out);
}

// round 9
// speedup vs baseline: 1.3316x; 1.0215x over previous
#include <cuda_runtime.h>
#include <cuda_bf16.h>
#include <cstdint>

#define N_NODES 100000
#define F_DIM   64
#define N_EDGES 1000000
#define ALPHA   0.1f
#define BETA    0.5f
#define CAP     64
#define N_GROUPS (N_NODES / 16)        // 6250 warps of 16 nodes

#define A_STRIDE 36                    // smem row stride in uint32 (144B)

// Scratch (__device__ globals; cudaMalloc forbidden)
__device__ int                 g_cnt[N_NODES];
__device__ unsigned long long  g_bucket[(size_t)N_NODES * CAP];   // (val<<32)|src
// support as packed bf16 planes: word j of row = cols (2j, 2j+1)
__device__ uint32_t            g_Ahi2[(size_t)N_NODES * 32];      // 12.8 MB
__device__ uint32_t            g_Alo2[(size_t)N_NODES * 32];      // 12.8 MB
// B fragments: [(kchunk*8+nb)*2+hl] -> 32 lanes x {b0,b1}
__device__ uint2               g_Bf[64 * 32];                     // 16 KB

// ---------------------------------------------------------------------------
// K0: zero counters + W' B-fragments (bf16 hi/lo, pre-packed)
// ---------------------------------------------------------------------------
__device__ __forceinline__ float wprime(const float* W, int k, int n) {
    return BETA * W[k * 64 + n] + ((k == n) ? (1.0f - BETA) : 0.0f);
}
__global__ void prep_kernel(const float* __restrict__ W) {
    int i = blockIdx.x * blockDim.x + threadIdx.x;
    if (i < N_NODES / 4)
        reinterpret_cast<int4*>(g_cnt)[i] = make_int4(0, 0, 0, 0);
    if (i < 1024) {                       // (c, nb, lane)
        int c    = i >> 8;
        int nb   = (i >> 5) & 7;
        int lane = i & 31;
        int n  = nb * 8 + (lane >> 2);
        int k0 = c * 16 + (lane & 3) * 2;
        float v[4] = { wprime(W, k0, n),     wprime(W, k0 + 1, n),
                       wprime(W, k0 + 8, n), wprime(W, k0 + 9, n) };
        uint32_t hp[2], lp[2];
        #pragma unroll
        for (int r = 0; r < 2; r++) {
            __nv_bfloat16 h0 = __float2bfloat16(v[r*2+0]);
            __nv_bfloat16 h1 = __float2bfloat16(v[r*2+1]);
            __nv_bfloat16 l0 = __float2bfloat16(v[r*2+0] - __bfloat162float(h0));
            __nv_bfloat16 l1 = __float2bfloat16(v[r*2+1] - __bfloat162float(h1));
            hp[r] = ((uint32_t)__bfloat16_as_ushort(h1) << 16) | __bfloat16_as_ushort(h0);
            lp[r] = ((uint32_t)__bfloat16_as_ushort(l1) << 16) | __bfloat16_as_ushort(l0);
        }
        int base = (c * 8 + nb) * 2;
        g_Bf[(base + 0) * 32 + lane] = make_uint2(hp[0], hp[1]);
        g_Bf[(base + 1) * 32 + lane] = make_uint2(lp[0], lp[1]);
    }
}

// ---------------------------------------------------------------------------
// K1: bucket fill — scalar, int atomics
// ---------------------------------------------------------------------------
__global__ void fill_kernel(const int*   __restrict__ src,
                            const int*   __restrict__ dst,
                            const float* __restrict__ val) {
    int e = blockIdx.x * blockDim.x + threadIdx.x;
    if (e >= N_EDGES) return;
    int d = dst[e];
    int pos = atomicAdd(&g_cnt[d], 1);
    if (pos < CAP) {
        unsigned long long p =
            ((unsigned long long)__float_as_uint((1.0f - ALPHA) * val[e]) << 32)
            | (unsigned int)src[e];
        g_bucket[(size_t)d * CAP + pos] = p;
    }
}

// ---------------------------------------------------------------------------
// K2: gather — one warp per node; coalesced packed hi/lo plane writes.
// ---------------------------------------------------------------------------
__global__ void __launch_bounds__(256) gather_kernel(const float2* __restrict__ feat2,
                                                     const float2* __restrict__ f02) {
    int node = (blockIdx.x * blockDim.x + threadIdx.x) >> 5;
    int lane = threadIdx.x & 31;
    if (node >= N_NODES) return;

    float2 fv = __ldg(&f02[(size_t)node * 32 + lane]);
    float ax = ALPHA * fv.x;
    float ay = ALPHA * fv.y;

    int cnt = min(g_cnt[node], CAP);
    const unsigned long long* bk = &g_bucket[(size_t)node * CAP];

    if (cnt > 0) {
        unsigned long long p  = bk[0];
        unsigned long long pn = (cnt > 1) ? bk[1] : 0ull;
        float2 f = feat2[(size_t)(unsigned)(p & 0xffffffffu) * 32 + lane];
        for (int e = 0; e < cnt; e++) {
            unsigned long long p2 = (e + 2 < cnt) ? bk[e + 2] : 0ull;
            float2 fn = feat2[(size_t)(unsigned)(pn & 0xffffffffu) * 32 + lane];
            float w = __uint_as_float((unsigned)(p >> 32));
            ax = fmaf(w, f.x, ax);
            ay = fmaf(w, f.y, ay);
            p = pn; pn = p2; f = fn;
        }
    }

    __nv_bfloat16 hx = __float2bfloat16(ax);
    __nv_bfloat16 hy = __float2bfloat16(ay);
    __nv_bfloat16 lx = __float2bfloat16(ax - __bfloat162float(hx));
    __nv_bfloat16 ly = __float2bfloat16(ay - __bfloat162float(hy));
    uint32_t hp = ((uint32_t)__bfloat16_as_ushort(hy) << 16) | __bfloat16_as_ushort(hx);
    uint32_t lp = ((uint32_t)__bfloat16_as_ushort(ly) << 16) | __bfloat16_as_ushort(lx);

    g_Ahi2[(size_t)node * 32 + lane] = hp;
    g_Alo2[(size_t)node * 32 + lane] = lp;
}

// ---------------------------------------------------------------------------
// K3: GEMM via mma.sync m16n8k16 bf16, 3-term split, + ReLU.
// Block = 256 thr / 8 warps = 128 nodes. A staged to smem (stride-36 rows,
// 144B -> ldmatrix conflict-free), fragments via ldmatrix.m8n8.x4.
// ---------------------------------------------------------------------------
__device__ __forceinline__ void mma16816(float& d0, float& d1, float& d2, float& d3,
                                         uint32_t a0, uint32_t a1, uint32_t a2, uint32_t a3,
                                         uint2 b) {
    asm volatile(
        "mma.sync.aligned.m16n8k16.row.col.f32.bf16.bf16.f32 "
        "{%0,%1,%2,%3}, {%4,%5,%6,%7}, {%8,%9}, {%0,%1,%2,%3};"
        : "+f"(d0), "+f"(d1), "+f"(d2), "+f"(d3)
        : "r"(a0), "r"(a1), "r"(a2), "r"(a3), "r"(b.x), "r"(b.y));
}

__global__ void __launch_bounds__(256) mma_kernel(float* __restrict__ out) {
    __shared__ uint32_t sh[2][128 * A_STRIDE];   // 36.9 KB

    int tid  = threadIdx.x, wid = tid >> 5, lane = tid & 31;
    int base = blockIdx.x * 128;

    // Stage A planes: 128 rows x 8 uint4 per plane; 4 uint4 per thread/plane
    #pragma unroll
    for (int p = 0; p < 2; p++) {
        const uint4* src = reinterpret_cast<const uint4*>(p ? g_Alo2 : g_Ahi2);
        #pragma unroll
        for (int i = 0; i < 4; i++) {
            int u   = tid + i * 256;       // 0..1023
            int row = u >> 3, w4 = u & 7;
            int node = base + row;
            uint4 v = (node < N_NODES) ? __ldg(&src[(size_t)node * 8 + w4])
                                       : make_uint4(0, 0, 0, 0);
            *reinterpret_cast<uint4*>(&sh[p][row * A_STRIDE + w4 * 4]) = v;
        }
    }
    __syncthreads();

    // ldmatrix addresses: lanes 0-7 rows0-7/col0, 8-15 rows8-15/col0,
    // 16-23 rows0-7/col8, 24-31 rows8-15/col8  (matches a0..a3 mapping)
    int row_l  = wid * 16 + (lane & 7) + ((lane >> 3) & 1) * 8;
    int colsel = (lane >> 4) * 4;      // uint32 offset for col 8..15 half

    uint32_t ah[4][4], al[4][4];
    #pragma unroll
    for (int c = 0; c < 4; c++) {
        uint32_t addr_h = (uint32_t)__cvta_generic_to_shared(
            &sh[0][row_l * A_STRIDE + c * 8 + colsel]);
        uint32_t addr_l = (uint32_t)__cvta_generic_to_shared(
            &sh[1][row_l * A_STRIDE + c * 8 + colsel]);
        asm volatile("ldmatrix.sync.aligned.m8n8.x4.shared.b16 {%0,%1,%2,%3}, [%4];"
            : "=r"(ah[c][0]), "=r"(ah[c][1]), "=r"(ah[c][2]), "=r"(ah[c][3])
            : "r"(addr_h));
        asm volatile("ldmatrix.sync.aligned.m8n8.x4.shared.b16 {%0,%1,%2,%3}, [%4];"
            : "=r"(al[c][0]), "=r"(al[c][1]), "=r"(al[c][2]), "=r"(al[c][3])
            : "r"(addr_l));
    }

    int grp = lane >> 2, qp = lane & 3;
    int row0 = base + wid * 16 + grp;       // rows row0, row0+8

    #pragma unroll
    for (int nb = 0; nb < 8; nb++) {
        float d0 = 0.f, d1 = 0.f, d2 = 0.f, d3 = 0.f;
        #pragma unroll
        for (int c = 0; c < 4; c++) {
            int bbase = (c * 8 + nb) * 2;
            uint2 bh = __ldg(&g_Bf[(bbase + 0) * 32 + lane]);
            uint2 bl = __ldg(&g_Bf[(bbase + 1) * 32 + lane]);
            mma16816(d0, d1, d2, d3, ah[c][0], ah[c][1], ah[c][2], ah[c][3], bh);
            mma16816(d0, d1, d2, d3, ah[c][0], ah[c][1], ah[c][2], ah[c][3], bl);
            mma16816(d0, d1, d2, d3, al[c][0], al[c][1], al[c][2], al[c][3], bh);
        }
        int col = nb * 8 + qp * 2;
        if (row0 < N_NODES) {
            *reinterpret_cast<float2*>(&out[(size_t)row0 * F_DIM + col]) =
                make_float2(fmaxf(d0, 0.f), fmaxf(d1, 0.f));
        }
        if (row0 + 8 < N_NODES) {
            *reinterpret_cast<float2*>(&out[(size_t)(row0 + 8) * F_DIM + col]) =
                make_float2(fmaxf(d2, 0.f), fmaxf(d3, 0.f));
        }
    }
}

// ---------------------------------------------------------------------------
// inputs: 0=features, 1=features0, 2=edge_src, 3=edge_dst, 4=edge_vals, 5=W
// ---------------------------------------------------------------------------
extern "C" void kernel_launch(void* const* d_in, const int* in_sizes, int n_in,
                              void* d_out, int out_size) {
    const float* features  = (const float*)d_in[0];
    const float* features0 = (const float*)d_in[1];
    const int*   edge_src  = (const int*)d_in[2];
    const int*   edge_dst  = (const int*)d_in[3];
    const float* edge_vals = (const float*)d_in[4];
    const float* W         = (const float*)d_in[5];
    float* out = (float*)d_out;

    prep_kernel<<<(N_NODES / 4 + 255) / 256, 256>>>(W);
    fill_kernel<<<(N_EDGES + 255) / 256, 256>>>(edge_src, edge_dst, edge_vals);

    long long gthreads = (long long)N_NODES * 32;
    gather_kernel<<<(int)((gthreads + 255) / 256), 256>>>(
        reinterpret_cast<const float2*>(features),
        reinterpret_cast<const float2*>(features0));

    mma_kernel<<<(N_NODES + 127) / 128, 256>>>(out);
}

// round 10
// speedup vs baseline: 1.4228x; 1.0685x over previous
#include <cuda_runtime.h>
#include <cuda_bf16.h>
#include <cstdint>

#define N_NODES 100000
#define F_DIM   64
#define N_EDGES 1000000
#define ALPHA   0.1f
#define BETA    0.5f
#define CAP     64

#define A_STRIDE 36                    // smem row stride in uint32 (144B)

// Scratch (__device__ globals; cudaMalloc forbidden)
__device__ int                 g_cnt[N_NODES];
__device__ unsigned long long  g_bucket[(size_t)N_NODES * CAP];   // (val<<32)|src
// support as packed bf16 planes: word j of row = REAL cols (j, j+32)
__device__ uint32_t            g_Ahi2[(size_t)N_NODES * 32];      // 12.8 MB
__device__ uint32_t            g_Alo2[(size_t)N_NODES * 32];      // 12.8 MB
// B fragments: [(kchunk*8+nb)*2+hl] -> 32 lanes x {b0,b1}, logical-k permuted
__device__ uint2               g_Bf[64 * 32];                     // 16 KB

// logical k (GEMM reduction index) -> real feature column
__host__ __device__ __forceinline__ int kperm(int k) {
    return (k & 1) ? (k >> 1) + 32 : (k >> 1);
}

// ---------------------------------------------------------------------------
// K0: zero counters + W' B-fragments (bf16 hi/lo), k-permuted to match the
//     gather's plane layout (word j = cols j, j+32).
// ---------------------------------------------------------------------------
__device__ __forceinline__ float wprime(const float* W, int k, int n) {
    return BETA * W[k * 64 + n] + ((k == n) ? (1.0f - BETA) : 0.0f);
}
__global__ void prep_kernel(const float* __restrict__ W) {
    int i = blockIdx.x * blockDim.x + threadIdx.x;
    if (i < N_NODES / 4)
        reinterpret_cast<int4*>(g_cnt)[i] = make_int4(0, 0, 0, 0);
    if (i < 1024) {                       // (c, nb, lane)
        int c    = i >> 8;
        int nb   = (i >> 5) & 7;
        int lane = i & 31;
        int n  = nb * 8 + (lane >> 2);
        int k0 = c * 16 + (lane & 3) * 2;
        float v[4] = { wprime(W, kperm(k0),     n), wprime(W, kperm(k0 + 1), n),
                       wprime(W, kperm(k0 + 8), n), wprime(W, kperm(k0 + 9), n) };
        uint32_t hp[2], lp[2];
        #pragma unroll
        for (int r = 0; r < 2; r++) {
            __nv_bfloat16 h0 = __float2bfloat16(v[r*2+0]);
            __nv_bfloat16 h1 = __float2bfloat16(v[r*2+1]);
            __nv_bfloat16 l0 = __float2bfloat16(v[r*2+0] - __bfloat162float(h0));
            __nv_bfloat16 l1 = __float2bfloat16(v[r*2+1] - __bfloat162float(h1));
            hp[r] = ((uint32_t)__bfloat16_as_ushort(h1) << 16) | __bfloat16_as_ushort(h0);
            lp[r] = ((uint32_t)__bfloat16_as_ushort(l1) << 16) | __bfloat16_as_ushort(l0);
        }
        int base = (c * 8 + nb) * 2;
        g_Bf[(base + 0) * 32 + lane] = make_uint2(hp[0], hp[1]);
        g_Bf[(base + 1) * 32 + lane] = make_uint2(lp[0], lp[1]);
    }
}

// ---------------------------------------------------------------------------
// K1: bucket fill — scalar, int atomics
// ---------------------------------------------------------------------------
__global__ void fill_kernel(const int*   __restrict__ src,
                            const int*   __restrict__ dst,
                            const float* __restrict__ val) {
    int e = blockIdx.x * blockDim.x + threadIdx.x;
    if (e >= N_EDGES) return;
    int d = dst[e];
    int pos = atomicAdd(&g_cnt[d], 1);
    if (pos < CAP) {
        unsigned long long p =
            ((unsigned long long)__float_as_uint((1.0f - ALPHA) * val[e]) << 32)
            | (unsigned int)src[e];
        g_bucket[(size_t)d * CAP + pos] = p;
    }
}

// ---------------------------------------------------------------------------
// K2: gather — one warp per node; 3-deep pipeline, scalar loads for MLP.
//     Lane owns cols (lane, lane+32); plane word lane = those two cols.
// ---------------------------------------------------------------------------
__global__ void __launch_bounds__(256) gather_kernel(const float* __restrict__ feat,
                                                     const float* __restrict__ f0) {
    int node = (blockIdx.x * blockDim.x + threadIdx.x) >> 5;
    int lane = threadIdx.x & 31;
    if (node >= N_NODES) return;

    size_t row = (size_t)node * F_DIM;
    float a0 = ALPHA * __ldg(&f0[row + lane]);
    float a1 = ALPHA * __ldg(&f0[row + 32 + lane]);

    int cnt = min(g_cnt[node], CAP);
    const unsigned long long* bk = &g_bucket[(size_t)node * CAP];

    if (cnt > 0) {
        int c1 = cnt - 1;
        unsigned long long p0 = bk[0];
        unsigned long long p1 = bk[min(1, c1)];
        unsigned long long p2 = bk[min(2, c1)];
        size_t s0 = (size_t)(unsigned)(p0 & 0xffffffffu) * F_DIM;
        size_t s1 = (size_t)(unsigned)(p1 & 0xffffffffu) * F_DIM;
        size_t s2 = (size_t)(unsigned)(p2 & 0xffffffffu) * F_DIM;
        float r0a = feat[s0 + lane], r0b = feat[s0 + 32 + lane];
        float r1a = feat[s1 + lane], r1b = feat[s1 + 32 + lane];
        float r2a = feat[s2 + lane], r2b = feat[s2 + 32 + lane];

        for (int e = 0; e < cnt; e++) {
            unsigned long long p3 = bk[min(e + 3, c1)];
            size_t s3 = (size_t)(unsigned)(p3 & 0xffffffffu) * F_DIM;
            float r3a = feat[s3 + lane];
            float r3b = feat[s3 + 32 + lane];
            float w = __uint_as_float((unsigned)(p0 >> 32));
            a0 = fmaf(w, r0a, a0);
            a1 = fmaf(w, r0b, a1);
            p0 = p1; p1 = p2; p2 = p3;
            r0a = r1a; r0b = r1b;
            r1a = r2a; r1b = r2b;
            r2a = r3a; r2b = r3b;
        }
    }

    __nv_bfloat16 hx = __float2bfloat16(a0);
    __nv_bfloat16 hy = __float2bfloat16(a1);
    __nv_bfloat16 lx = __float2bfloat16(a0 - __bfloat162float(hx));
    __nv_bfloat16 ly = __float2bfloat16(a1 - __bfloat162float(hy));
    uint32_t hp = ((uint32_t)__bfloat16_as_ushort(hy) << 16) | __bfloat16_as_ushort(hx);
    uint32_t lp = ((uint32_t)__bfloat16_as_ushort(ly) << 16) | __bfloat16_as_ushort(lx);
    g_Ahi2[(size_t)node * 32 + lane] = hp;   // logical k-pair (2*lane, 2*lane+1)
    g_Alo2[(size_t)node * 32 + lane] = lp;
}

// ---------------------------------------------------------------------------
// K3: GEMM via mma.sync m16n8k16 bf16, 3-term split, + ReLU.
// 128 thr / 4 warps, 32 nodes per warp (2 m16 tiles share every B load).
// ---------------------------------------------------------------------------
__device__ __forceinline__ void mma16816(float& d0, float& d1, float& d2, float& d3,
                                         uint32_t a0, uint32_t a1, uint32_t a2, uint32_t a3,
                                         uint2 b) {
    asm volatile(
        "mma.sync.aligned.m16n8k16.row.col.f32.bf16.bf16.f32 "
        "{%0,%1,%2,%3}, {%4,%5,%6,%7}, {%8,%9}, {%0,%1,%2,%3};"
        : "+f"(d0), "+f"(d1), "+f"(d2), "+f"(d3)
        : "r"(a0), "r"(a1), "r"(a2), "r"(a3), "r"(b.x), "r"(b.y));
}

__global__ void __launch_bounds__(128) mma_kernel(float* __restrict__ out) {
    __shared__ uint32_t sh[2][128 * A_STRIDE];   // 36.9 KB

    int tid  = threadIdx.x, wid = tid >> 5, lane = tid & 31;
    int base = blockIdx.x * 128;

    #pragma unroll
    for (int p = 0; p < 2; p++) {
        const uint4* src = reinterpret_cast<const uint4*>(p ? g_Alo2 : g_Ahi2);
        #pragma unroll
        for (int i = 0; i < 8; i++) {
            int u   = tid + i * 128;       // 0..1023
            int row = u >> 3, w4 = u & 7;
            int node = base + row;
            uint4 v = (node < N_NODES) ? __ldg(&src[(size_t)node * 8 + w4])
                                       : make_uint4(0, 0, 0, 0);
            *reinterpret_cast<uint4*>(&sh[p][row * A_STRIDE + w4 * 4]) = v;
        }
    }
    __syncthreads();

    int lrow   = (lane & 7) + ((lane >> 3) & 1) * 8;
    int colsel = (lane >> 4) * 4;
    uint32_t ah[2][4][4], al[2][4][4];
    #pragma unroll
    for (int t = 0; t < 2; t++) {
        int row_l = wid * 32 + t * 16 + lrow;
        #pragma unroll
        for (int c = 0; c < 4; c++) {
            uint32_t addr_h = (uint32_t)__cvta_generic_to_shared(
                &sh[0][row_l * A_STRIDE + c * 8 + colsel]);
            uint32_t addr_l = (uint32_t)__cvta_generic_to_shared(
                &sh[1][row_l * A_STRIDE + c * 8 + colsel]);
            asm volatile("ldmatrix.sync.aligned.m8n8.x4.shared.b16 {%0,%1,%2,%3}, [%4];"
                : "=r"(ah[t][c][0]), "=r"(ah[t][c][1]), "=r"(ah[t][c][2]), "=r"(ah[t][c][3])
                : "r"(addr_h));
            asm volatile("ldmatrix.sync.aligned.m8n8.x4.shared.b16 {%0,%1,%2,%3}, [%4];"
                : "=r"(al[t][c][0]), "=r"(al[t][c][1]), "=r"(al[t][c][2]), "=r"(al[t][c][3])
                : "r"(addr_l));
        }
    }

    int grp = lane >> 2, qp = lane & 3;

    #pragma unroll
    for (int nb = 0; nb < 8; nb++) {
        float d[2][4];
        #pragma unroll
        for (int t = 0; t < 2; t++)
            d[t][0] = d[t][1] = d[t][2] = d[t][3] = 0.f;

        #pragma unroll
        for (int c = 0; c < 4; c++) {
            int bbase = (c * 8 + nb) * 2;
            uint2 bh = __ldg(&g_Bf[(bbase + 0) * 32 + lane]);
            uint2 bl = __ldg(&g_Bf[(bbase + 1) * 32 + lane]);
            #pragma unroll
            for (int t = 0; t < 2; t++) {
                mma16816(d[t][0], d[t][1], d[t][2], d[t][3],
                         ah[t][c][0], ah[t][c][1], ah[t][c][2], ah[t][c][3], bh);
                mma16816(d[t][0], d[t][1], d[t][2], d[t][3],
                         ah[t][c][0], ah[t][c][1], ah[t][c][2], ah[t][c][3], bl);
                mma16816(d[t][0], d[t][1], d[t][2], d[t][3],
                         al[t][c][0], al[t][c][1], al[t][c][2], al[t][c][3], bh);
            }
        }
        int col = nb * 8 + qp * 2;
        #pragma unroll
        for (int t = 0; t < 2; t++) {
            int row0 = base + wid * 32 + t * 16 + grp;
            if (row0 < N_NODES)
                *reinterpret_cast<float2*>(&out[(size_t)row0 * F_DIM + col]) =
                    make_float2(fmaxf(d[t][0], 0.f), fmaxf(d[t][1], 0.f));
            if (row0 + 8 < N_NODES)
                *reinterpret_cast<float2*>(&out[(size_t)(row0 + 8) * F_DIM + col]) =
                    make_float2(fmaxf(d[t][2], 0.f), fmaxf(d[t][3], 0.f));
        }
    }
}

// ---------------------------------------------------------------------------
// inputs: 0=features, 1=features0, 2=edge_src, 3=edge_dst, 4=edge_vals, 5=W
// ---------------------------------------------------------------------------
extern "C" void kernel_launch(void* const* d_in, const int* in_sizes, int n_in,
                              void* d_out, int out_size) {
    const float* features  = (const float*)d_in[0];
    const float* features0 = (const float*)d_in[1];
    const int*   edge_src  = (const int*)d_in[2];
    const int*   edge_dst  = (const int*)d_in[3];
    const float* edge_vals = (const float*)d_in[4];
    const float* W         = (const float*)d_in[5];
    float* out = (float*)d_out;

    prep_kernel<<<(N_NODES / 4 + 255) / 256, 256>>>(W);
    fill_kernel<<<(N_EDGES + 255) / 256, 256>>>(edge_src, edge_dst, edge_vals);

    long long gthreads = (long long)N_NODES * 32;
    gather_kernel<<<(int)((gthreads + 255) / 256), 256>>>(features, features0);

    mma_kernel<<<(N_NODES + 127) / 128, 128>>>(out);
}